// round 1
// baseline (speedup 1.0000x reference)
#include <cuda_runtime.h>
#include <math.h>

#define EPSF 1e-8f
#define RCUT 4.8f
#define NBC 64
#define NN 20
#define HID 64

// ---- dynamic shared layout (floats) ----
// weights region (shared by all 4 lanes)
static constexpr int OW0   = 0;      // W0 padded [15][65] = 975 -> pad 976
static constexpr int OW1   = 976;    // W1 padded [64][65] = 4160
static constexpr int OW2   = 5136;   // 64
static constexpr int OB0   = 5200;   // 64
static constexpr int OB1   = 5264;   // 64
static constexpr int OMISC = 5328;   // [0]=b2, [1..3]=a_j=f1^2+eps, [4..6]=p_j=f2^2+eps ; pad 16
static constexpr int WFL   = 5344;

// per-lane region (offsets relative to lane base)
static constexpr int LR    = 0;      // R[64]
static constexpr int LSEL  = 64;     // int sel[20] (stored via cast), pad to 84
static constexpr int LNDN  = 84;     // ndn[20][3] = 60
static constexpr int LNOR  = 144;    // nor[20][9] = 180
static constexpr int LNEWR = 324;    // 20
static constexpr int LFCR  = 344;    // 20
static constexpr int LSO   = 364;    // orientation 9, pad 12
static constexpr int LFEAT = 376;    // featT [15][20] = 300  (row stride 20, float4-aligned)
static constexpr int LH1   = 676;    // h1T [64][20] = 1280
static constexpr int LH2   = 1956;   // h2T [64][20] = 1280
static constexpr int LGF   = 3236;   // gfeat [20][16] = 320
static constexpr int LGZ   = 3556;   // 20
static constexpr int LDN   = 3576;   // 20
static constexpr int LENC  = 3596;   // 20
static constexpr int LPN   = 3616;   // 20
static constexpr int LGO   = 3636;   // 9, pad 12
static constexpr int LSC   = 3648;   // [0]=S, [1]=F, pad 4
static constexpr int LANE_FLOATS = 3652;

static constexpr int SMEM_FLOATS = WFL + 4 * LANE_FLOATS;   // 19952 floats = 79808 B

__global__ __launch_bounds__(256, 2)
void ep_kernel(const float* __restrict__ dr,
               const float* __restrict__ orientation,
               const float* __restrict__ n_or,
               const float* __restrict__ W0, const float* __restrict__ b0,
               const float* __restrict__ W1, const float* __restrict__ b1,
               const float* __restrict__ W2, const float* __restrict__ b2,
               const float* __restrict__ f1, const float* __restrict__ f2,
               float* __restrict__ out, int B)
{
    extern __shared__ float sm[];
    const int tid = threadIdx.x;

    // ---- stage weights into padded shared ----
    for (int idx = tid; idx < 15 * 64; idx += 256) {
        int i = idx >> 6, j = idx & 63;
        sm[OW0 + i * 65 + j] = W0[idx];
    }
    for (int idx = tid; idx < 64 * 64; idx += 256) {
        int k = idx >> 6, j = idx & 63;
        sm[OW1 + k * 65 + j] = W1[idx];
    }
    for (int idx = tid; idx < 64; idx += 256) {
        sm[OW2 + idx] = W2[idx];
        sm[OB0 + idx] = b0[idx];
        sm[OB1 + idx] = b1[idx];
    }
    if (tid == 0) {
        sm[OMISC + 0] = b2[0];
        #pragma unroll
        for (int j = 0; j < 3; j++) {
            float a = f1[j]; sm[OMISC + 1 + j] = a * a + EPSF;
            float p = f2[j]; sm[OMISC + 4 + j] = p * p + EPSF;
        }
    }

    const int lane = tid >> 6;          // 0..3
    const int t    = tid & 63;          // 0..63
    const int batch0 = blockIdx.x * 4 + lane;
    const bool wr = batch0 < B;
    const int batch = wr ? batch0 : 0;
    float* L = sm + WFL + lane * LANE_FLOATS;
    int* sel = (int*)(L + LSEL);

    // ---- phase 1: radii + orientation stage ----
    {
        const float* d = dr + (size_t)batch * NBC * 3 + t * 3;
        float x = d[0] + EPSF, y = d[1] + EPSF, z = d[2] + EPSF;
        L[LR + t] = sqrtf(x * x + y * y + z * z);
        if (t < 9) L[LSO + t] = orientation[(size_t)batch * 9 + t];
    }
    __syncthreads();

    // ---- phase 2: stable rank (matches stable argsort) ----
    {
        float Rt = L[LR + t];
        int rank = 0;
        #pragma unroll 8
        for (int u = 0; u < NBC; u++) {
            float Ru = L[LR + u];
            rank += (Ru < Rt) || (Ru == Rt && u < t);
        }
        if (rank < NN) sel[rank] = t;
    }
    __syncthreads();

    // ---- phase 3: gather selected neighbors ----
    if (t < NN) {
        int s = sel[t];
        float Rv = L[LR + s];
        L[LNEWR + t] = Rv;
        const float* d = dr + (size_t)batch * NBC * 3 + s * 3;
        float inv = 1.0f / Rv;
        L[LNDN + t * 3 + 0] = (d[0] + EPSF) * inv;
        L[LNDN + t * 3 + 1] = (d[1] + EPSF) * inv;
        L[LNDN + t * 3 + 2] = (d[2] + EPSF) * inv;
        L[LFCR + t] = (Rv > RCUT) ? 0.0f : (0.5f * cospif(Rv * (1.0f / RCUT)) + 0.5f);
        const float* np_ = n_or + ((size_t)batch * NBC + s) * 9;
        #pragma unroll
        for (int e = 0; e < 9; e++) L[LNOR + t * 9 + e] = np_[e];
    }
    __syncthreads();

    // ---- phase 4: featT[i][n] (i feature index 0..14, n neighbor) ----
    for (int p = t; p < NN * 15; p += 64) {
        int n = p / 15, i = p - n * 15;
        const float* nd = L + LNDN + n * 3;
        const float* NO = L + LNOR + n * 9;
        const float* O  = L + LSO;
        float v;
        if (i < 3) {                                     // dr_o[h=i] = sum_k ndn[k]*O[k,i]
            v = nd[0] * O[0 * 3 + i] + nd[1] * O[1 * 3 + i] + nd[2] * O[2 * 3 + i];
        } else if (i < 6) {                              // dr_no[h] = sum_k ndn[k]*N[k,h]
            int h = i - 3;
            v = nd[0] * NO[0 * 3 + h] + nd[1] * NO[1 * 3 + h] + nd[2] * NO[2 * 3 + h];
        } else {                                         // o_no[l,m] = sum_h O[h,l]*N[h,m]
            int l = (i - 6) / 3, m = (i - 6) % 3;
            v = O[0 * 3 + l] * NO[0 * 3 + m] + O[1 * 3 + l] * NO[1 * 3 + m] + O[2 * 3 + l] * NO[2 * 3 + m];
        }
        L[LFEAT + i * NN + n] = v;
    }
    __syncthreads();

    // ---- phase 5: h1 = tanh(feat @ W0 + b0), stored transposed [j][n] ----
    {
        float acc[NN];
        float bb = sm[OB0 + t];
        #pragma unroll
        for (int n = 0; n < NN; n++) acc[n] = bb;
        #pragma unroll
        for (int i = 0; i < 15; i++) {
            float w = sm[OW0 + i * 65 + t];
            const float4* fr = (const float4*)(L + LFEAT + i * NN);
            #pragma unroll
            for (int q = 0; q < 5; q++) {
                float4 f = fr[q];
                acc[4 * q + 0] += f.x * w;
                acc[4 * q + 1] += f.y * w;
                acc[4 * q + 2] += f.z * w;
                acc[4 * q + 3] += f.w * w;
            }
        }
        #pragma unroll
        for (int n = 0; n < NN; n++) L[LH1 + t * NN + n] = tanhf(acc[n]);
    }
    __syncthreads();

    // ---- phase 6: h2 = tanh(h1 @ W1 + b1), transposed ----
    {
        float acc[NN];
        float bb = sm[OB1 + t];
        #pragma unroll
        for (int n = 0; n < NN; n++) acc[n] = bb;
        #pragma unroll 4
        for (int k = 0; k < HID; k++) {
            float w = sm[OW1 + k * 65 + t];
            const float4* fr = (const float4*)(L + LH1 + k * NN);
            #pragma unroll
            for (int q = 0; q < 5; q++) {
                float4 f = fr[q];
                acc[4 * q + 0] += f.x * w;
                acc[4 * q + 1] += f.y * w;
                acc[4 * q + 2] += f.z * w;
                acc[4 * q + 3] += f.w * w;
            }
        }
        #pragma unroll
        for (int n = 0; n < NN; n++) L[LH2 + t * NN + n] = tanhf(acc[n]);
    }
    __syncthreads();

    // ---- phase 7: z, enc, power-law prior pieces (per neighbor) ----
    if (t < NN) {
        float z = sm[OMISC + 0];
        #pragma unroll 8
        for (int j = 0; j < HID; j++) z += L[LH2 + j * NN + t] * sm[OW2 + j];
        float enc = tanhf(z);
        float e = enc * enc + EPSF;
        float Rm = L[LNEWR + t] - e;
        float P = 0.f, Dsum = 0.f;
        #pragma unroll
        for (int j = 0; j < 3; j++) {
            float a = sm[OMISC + 1 + j], p = sm[OMISC + 4 + j];
            float u = a * Rm;
            float tt = exp2f(-p * log2f(u));     // (a*(R-e))^(-p)
            P += tt;
            Dsum += p * tt;
        }
        L[LPN + t]  = P;
        L[LDN + t]  = Dsum / Rm;                 // dE/de_n / F
        L[LENC + t] = enc;
    }
    __syncthreads();
    if (t == 0) {
        float S = 0.f, F = 0.f;
        #pragma unroll
        for (int n = 0; n < NN; n++) { S += L[LPN + n]; F += L[LFCR + n]; }
        L[LSC + 0] = S;
        L[LSC + 1] = F;
    }
    __syncthreads();
    if (t < NN) {
        float F = L[LSC + 1];
        float enc = L[LENC + t];
        L[LGZ + t] = F * L[LDN + t] * 2.f * enc * (1.f - enc * enc);
    }
    __syncthreads();

    // ---- phase 8: g_a2 overwrites h2T ----
    {
        float w2 = sm[OW2 + t];
        #pragma unroll
        for (int n = 0; n < NN; n++) {
            float h2v = L[LH2 + t * NN + n];
            L[LH2 + t * NN + n] = L[LGZ + n] * w2 * (1.f - h2v * h2v);
        }
    }
    __syncthreads();

    // ---- phase 9: g_h1 = g_a2 @ W1^T ; g_a1 overwrites h1T ----
    {
        float acc[NN];
        #pragma unroll
        for (int n = 0; n < NN; n++) acc[n] = 0.f;
        #pragma unroll 4
        for (int j = 0; j < HID; j++) {
            float w = sm[OW1 + t * 65 + j];
            const float4* fr = (const float4*)(L + LH2 + j * NN);
            #pragma unroll
            for (int q = 0; q < 5; q++) {
                float4 f = fr[q];
                acc[4 * q + 0] += f.x * w;
                acc[4 * q + 1] += f.y * w;
                acc[4 * q + 2] += f.z * w;
                acc[4 * q + 3] += f.w * w;
            }
        }
        #pragma unroll
        for (int n = 0; n < NN; n++) {
            float h1v = L[LH1 + t * NN + n];
            L[LH1 + t * NN + n] = acc[n] * (1.f - h1v * h1v);
        }
    }
    __syncthreads();

    // ---- phase 10: g_feat[n][i] = sum_k g_a1[k][n] * W0[i][k] ----
    for (int p = t; p < NN * 15; p += 64) {
        int n = p / 15, i = p - n * 15;
        float s2 = 0.f;
        #pragma unroll 8
        for (int k = 0; k < HID; k++) s2 += L[LH1 + k * NN + n] * sm[OW0 + i * 65 + k];
        L[LGF + n * 16 + i] = s2;
    }
    __syncthreads();

    // ---- phase 11: force, gO, energy ----
    if (t < 3) {
        float f = 0.f;
        const float* O = L + LSO;
        for (int n = 0; n < NN; n++) {
            const float* g  = L + LGF + n * 16;
            const float* NO = L + LNOR + n * 9;
            f += g[0] * O[t * 3 + 0] + g[1] * O[t * 3 + 1] + g[2] * O[t * 3 + 2];
            f += g[3] * NO[t * 3 + 0] + g[4] * NO[t * 3 + 1] + g[5] * NO[t * 3 + 2];
        }
        if (wr) out[(size_t)batch * 3 + t] = f;
    }
    if (t >= 4 && t < 13) {
        int a = (t - 4) / 3, bb = (t - 4) % 3;
        float g2 = 0.f;
        for (int n = 0; n < NN; n++) {
            const float* g  = L + LGF + n * 16;
            const float* NO = L + LNOR + n * 9;
            g2 += L[LNDN + n * 3 + a] * g[bb];
            g2 += g[6 + 3 * bb + 0] * NO[a * 3 + 0]
                + g[6 + 3 * bb + 1] * NO[a * 3 + 1]
                + g[6 + 3 * bb + 2] * NO[a * 3 + 2];
        }
        L[LGO + a * 3 + bb] = g2;
    }
    if (t < NN && wr) {
        out[(size_t)6 * B + (size_t)batch * NN + t] = L[LSC + 0] * L[LFCR + t];
    }
    __syncthreads();
    if (t == 0 && wr) {
        const float* gO = L + LGO;
        const float* O  = L + LSO;
        float tx = 0.f, ty = 0.f, tz = 0.f;
        #pragma unroll
        for (int c = 0; c < 3; c++) {
            float u0 = gO[0 * 3 + c], u1 = gO[1 * 3 + c], u2 = gO[2 * 3 + c];
            float v0 = O[0 * 3 + c],  v1 = O[1 * 3 + c],  v2 = O[2 * 3 + c];
            tx += u1 * v2 - u2 * v1;
            ty += u2 * v0 - u0 * v2;
            tz += u0 * v1 - u1 * v0;
        }
        out[(size_t)3 * B + (size_t)batch * 3 + 0] = tx;
        out[(size_t)3 * B + (size_t)batch * 3 + 1] = ty;
        out[(size_t)3 * B + (size_t)batch * 3 + 2] = tz;
    }
}

extern "C" void kernel_launch(void* const* d_in, const int* in_sizes, int n_in,
                              void* d_out, int out_size) {
    const float* dr  = (const float*)d_in[0];
    const float* ori = (const float*)d_in[1];
    const float* nor = (const float*)d_in[2];
    const float* W0  = (const float*)d_in[3];
    const float* b0  = (const float*)d_in[4];
    const float* W1  = (const float*)d_in[5];
    const float* b1  = (const float*)d_in[6];
    const float* W2  = (const float*)d_in[7];
    const float* b2  = (const float*)d_in[8];
    const float* f1  = (const float*)d_in[9];
    const float* f2  = (const float*)d_in[10];
    float* out = (float*)d_out;

    int B = in_sizes[0] / (NBC * 3);
    int blocks = (B + 3) / 4;
    size_t shmem = (size_t)SMEM_FLOATS * sizeof(float);
    cudaFuncSetAttribute(ep_kernel, cudaFuncAttributeMaxDynamicSharedMemorySize, (int)shmem);
    ep_kernel<<<blocks, 256, shmem>>>(dr, ori, nor, W0, b0, W1, b1, W2, b2, f1, f2, out, B);
}